// round 6
// baseline (speedup 1.0000x reference)
#include <cuda_runtime.h>
#include <cstdint>
#include <cstddef>

#define FEAT     832            // 64 * (1+3+9)
#define NPATH    15
#define WSZ      262144         // 64*64*64 weights per path
#define NSTEPS   (NPATH*64)     // 960
#define TB       8              // batch elems per CTA
#define NT       256            // threads per CTA (8 warps; warp = 1 elem)
#define PROW     12             // floats per P row (9 used + pad, 16B aligned)
#define PESTRIDE 772            // 64*PROW + 4
#define WBUF     4096           // floats per W step buffer (64 b x 64 c)

__constant__ int c_L1[NPATH] = {0,0,0,1,1,1,1,1,1,2,2,2,2,2,2};
__constant__ int c_L2[NPATH] = {0,1,2,0,1,1,1,2,2,0,1,1,2,2,2};
__constant__ int c_LO[NPATH] = {0,1,2,1,2,0,1,1,2,2,1,2,2,0,1};

// Transposed weights: g_wt[(p*64 + a)*4096 + b*64 + c]
__device__ float g_wt[NPATH * WSZ];

typedef unsigned long long ull;

__device__ __forceinline__ void ffma2(ull &d, ull a, ull b) {
    asm("fma.rn.f32x2 %0, %1, %2, %0;" : "+l"(d) : "l"(a), "l"(b));
}
__device__ __forceinline__ ull packf2(float x, float y) {
    ull r; asm("mov.b64 %0, {%1,%2};" : "=l"(r) : "f"(x), "f"(y)); return r;
}
__device__ __forceinline__ void unpackf2(ull v, float &x, float &y) {
    asm("mov.b64 {%0,%1}, %2;" : "=f"(x), "=f"(y) : "l"(v));
}
__device__ __forceinline__ uint32_t smem_u32(const void* p) {
    uint32_t a;
    asm("{ .reg .u64 t; cvta.to.shared.u64 t, %1; cvt.u32.u64 %0, t; }" : "=r"(a) : "l"(p));
    return a;
}
__device__ __forceinline__ void cpasync16(uint32_t dst, const void* src) {
    asm volatile("cp.async.cg.shared.global [%0], [%1], 16;" :: "r"(dst), "l"(src));
}

// ---------------- transpose kernel: wgt[p][c][a*64+b] -> g_wt[(p*64+a)][b][c] ----
__global__ void __launch_bounds__(256)
tp_transpose(const float* __restrict__ wgt)
{
    __shared__ float t[64*65];
    const int pa = blockIdx.x;              // 0..959
    const int p = pa >> 6, a = pa & 63;
    const float* src = wgt + (size_t)p*WSZ + (size_t)a*64;
    float* dst = g_wt + (size_t)pa*WBUF;
    const int tid = threadIdx.x;
    const int c = tid >> 2, bq = tid & 3;   // c 0..63, 16 b's per thread
    #pragma unroll
    for (int k = 0; k < 4; ++k) {
        float4 v = *(const float4*)(src + (size_t)c*4096 + bq*16 + k*4);
        int b = bq*16 + k*4;
        t[c*65+b] = v.x; t[c*65+b+1] = v.y; t[c*65+b+2] = v.z; t[c*65+b+3] = v.w;
    }
    __syncthreads();
    const int b2 = tid >> 2, cq = tid & 3;
    #pragma unroll
    for (int k = 0; k < 4; ++k) {
        int c0 = cq*16 + k*4;
        float4 v = make_float4(t[(c0+0)*65 + b2], t[(c0+1)*65 + b2],
                               t[(c0+2)*65 + b2], t[(c0+3)*65 + b2]);
        *(float4*)(dst + b2*64 + c0) = v;
    }
}

// ---------------- main kernel --------------------------------------------------
// smem floats: As 8*832 | Bs 8*832 | W 2*4096 | P 8*772  = 27680 floats (110.7KB)
#define SMEM_FLOATS (2*TB*FEAT + 2*WBUF + TB*PESTRIDE)
#define SMEM_BYTES  (SMEM_FLOATS*4)

__global__ void __launch_bounds__(NT, 2)
tp_main(const float* __restrict__ x1, const float* __restrict__ x2,
        float* __restrict__ out)
{
    extern __shared__ float sm[];
    float* As = sm;                       // [TB][832]
    float* Bs = As + TB*FEAT;
    float* Wb = Bs + TB*FEAT;             // 2 x [64 b][64 c]
    float* Ps = Wb + 2*WBUF;              // [TB][PESTRIDE]

    const int tid = threadIdx.x;
    const int w   = tid >> 5;             // warp 0..7 == elem within tile
    const int l   = tid & 31;             // lane; owns channels 2l, 2l+1
    const int blk = blockIdx.x;

    // ---- tile load ----
    {
        const float4* g1 = (const float4*)(x1 + (size_t)blk*TB*FEAT);
        const float4* g2 = (const float4*)(x2 + (size_t)blk*TB*FEAT);
        float4* s1 = (float4*)As; float4* s2 = (float4*)Bs;
        const int nv = TB*FEAT/4;         // 1664
        for (int i = tid; i < nv; i += NT) { s1[i] = g1[i]; s2[i] = g2[i]; }
    }

    // ---- accumulators: 2 channels x {1,3,9} ----
    float acc0[2] = {0,0};
    ull   a1p[2] = {0,0};
    float a1s[2] = {0,0};
    ull   a2p[2][4] = {{0,0,0,0},{0,0,0,0}};
    float a2s[2] = {0,0};

    // ---- W copy machinery (each thread copies 64B = 4 x 16B) ----
    const uint32_t wsm0 = smem_u32(Wb) + tid*64;
    const float* wtsrc0 = g_wt + (size_t)tid*16;

    // issue copy for step 0 into buffer 0
    {
        const float* s = wtsrc0;
        #pragma unroll
        for (int k = 0; k < 4; ++k) cpasync16(wsm0 + k*16, s + k*4);
        asm volatile("cp.async.commit_group;");
    }
    __syncthreads();   // tile load visible before pair phase

    int p = 0, a = 0;
    #pragma unroll 1
    for (int s = 0; s < NSTEPS; ++s) {
        // prefetch next step's W into the other buffer
        if (s + 1 < NSTEPS) {
            const float* src = wtsrc0 + (size_t)(s+1)*WBUF;
            const uint32_t dst = wsm0 + ((s+1)&1)*(WBUF*4);
            #pragma unroll
            for (int k = 0; k < 4; ++k) cpasync16(dst + k*16, src + k*4);
        }
        asm volatile("cp.async.commit_group;");

        const int L1 = c_L1[p], L2 = c_L2[p], LO = c_LO[p];
        const int aoff = (L1==0) ? a : ((L1==1) ? (64 + a*3) : (256 + a*9));

        // ---- pair phase: 512 rows / 256 threads = 2 rows each ----
        #pragma unroll
        for (int it = 0; it < 2; ++it) {
            const int pr = tid + it*NT;               // 0..511
            const int tb = pr >> 6, b = pr & 63;
            const float* Aa = As + tb*FEAT + aoff;
            const float* Bv = Bs + tb*FEAT + ((L2==0) ? b : ((L2==1) ? (64 + b*3) : (256 + b*9)));
            float* Pdst = Ps + tb*PESTRIDE + b*PROW;
            float P[9];
            switch (p) {
            case 0:  P[0] = Aa[0]*Bv[0]; break;
            case 1:  { float v=Aa[0]; P[0]=v*Bv[0]; P[1]=v*Bv[1]; P[2]=v*Bv[2]; } break;
            case 2:  {
                       float v=Aa[0];
                       #pragma unroll
                       for (int j=0;j<9;++j) P[j]=v*Bv[j];
                     } break;
            case 3:  { float v=Bv[0]; P[0]=Aa[0]*v; P[1]=Aa[1]*v; P[2]=Aa[2]*v; } break;
            case 4:  { float u0=Aa[0],u1=Aa[1],u2=Aa[2],v0=Bv[0],v1=Bv[1],v2=Bv[2];
                       P[0]=u0*v0;P[1]=u0*v1;P[2]=u0*v2;
                       P[3]=u1*v0;P[4]=u1*v1;P[5]=u1*v2;
                       P[6]=u2*v0;P[7]=u2*v1;P[8]=u2*v2; } break;
            case 5:  P[0] = Aa[0]*Bv[0] + Aa[1]*Bv[1] + Aa[2]*Bv[2]; break;
            case 6:  { float u0=Aa[0],u1=Aa[1],u2=Aa[2],v0=Bv[0],v1=Bv[1],v2=Bv[2];
                       P[0]=u1*v2-u2*v1; P[1]=u2*v0-u0*v2; P[2]=u0*v1-u1*v0; } break;
            case 7:  { float u0=Aa[0],u1=Aa[1],u2=Aa[2];
                       P[0]=u0*Bv[0]+u1*Bv[1]+u2*Bv[2];
                       P[1]=u0*Bv[3]+u1*Bv[4]+u2*Bv[5];
                       P[2]=u0*Bv[6]+u1*Bv[7]+u2*Bv[8]; } break;
            case 8:  {
                       float u0=Aa[0],u1=Aa[1],u2=Aa[2];
                       #pragma unroll
                       for (int q=0;q<3;++q) {
                           float v0=Bv[q*3],v1=Bv[q*3+1],v2=Bv[q*3+2];
                           P[q*3+0]=u1*v2-u2*v1; P[q*3+1]=u2*v0-u0*v2; P[q*3+2]=u0*v1-u1*v0;
                       }
                     } break;
            case 9:  {
                       float v=Bv[0];
                       #pragma unroll
                       for (int j=0;j<9;++j) P[j]=Aa[j]*v;
                     } break;
            case 10: { float v0=Bv[0],v1=Bv[1],v2=Bv[2];
                       P[0]=Aa[0]*v0+Aa[1]*v1+Aa[2]*v2;
                       P[1]=Aa[3]*v0+Aa[4]*v1+Aa[5]*v2;
                       P[2]=Aa[6]*v0+Aa[7]*v1+Aa[8]*v2; } break;
            case 11: {
                       float v0=Bv[0],v1=Bv[1],v2=Bv[2];
                       #pragma unroll
                       for (int d=0;d<3;++d) {
                           float u0=Aa[d*3],u1=Aa[d*3+1],u2=Aa[d*3+2];
                           P[d*3+0]=u1*v2-u2*v1; P[d*3+1]=u2*v0-u0*v2; P[d*3+2]=u0*v1-u1*v0;
                       }
                     } break;
            case 12: {
                       #pragma unroll
                       for (int d=0;d<3;++d) {
                           float u0=Aa[d*3],u1=Aa[d*3+1],u2=Aa[d*3+2];
                           #pragma unroll
                           for (int f=0;f<3;++f)
                               P[d*3+f]=u0*Bv[f*3]+u1*Bv[f*3+1]+u2*Bv[f*3+2];
                       }
                     } break;
            case 13: {
                       float v=0.f;
                       #pragma unroll
                       for (int j=0;j<9;++j) v += Aa[j]*Bv[j];
                       P[0]=v;
                     } break;
            default: { // 14: antisymmetric part of M[d][f] = dot(A2[d,:], B2[f,:])
                       float M01 = Aa[0]*Bv[3]+Aa[1]*Bv[4]+Aa[2]*Bv[5];
                       float M02 = Aa[0]*Bv[6]+Aa[1]*Bv[7]+Aa[2]*Bv[8];
                       float M10 = Aa[3]*Bv[0]+Aa[4]*Bv[1]+Aa[5]*Bv[2];
                       float M12 = Aa[3]*Bv[6]+Aa[4]*Bv[7]+Aa[5]*Bv[8];
                       float M20 = Aa[6]*Bv[0]+Aa[7]*Bv[1]+Aa[8]*Bv[2];
                       float M21 = Aa[6]*Bv[3]+Aa[7]*Bv[4]+Aa[8]*Bv[5];
                       P[0]=M12-M21; P[1]=M20-M02; P[2]=M01-M10; } break;
            }
            if (LO == 2) {
                *(float4*)Pdst     = make_float4(P[0],P[1],P[2],P[3]);
                *(float4*)(Pdst+4) = make_float4(P[4],P[5],P[6],P[7]);
                Pdst[8] = P[8];
            } else if (LO == 1) {
                *(float4*)Pdst = make_float4(P[0],P[1],P[2],0.f);
            } else {
                Pdst[0] = P[0];
            }
        }

        asm volatile("cp.async.wait_group 1;");   // W(s) landed; W(s+1) may fly
        __syncthreads();

        // ---- accumulate: warp w handles elem w, channels 2l, 2l+1 ----
        const float* Pp   = Ps + w*PESTRIDE;
        const float* Wcur = Wb + (s&1)*WBUF;      // [b][64 c]
        if (LO == 2) {
            #pragma unroll 2
            for (int b = 0; b < 64; ++b) {
                ulonglong2 q0 = *(const ulonglong2*)(Pp + b*PROW);      // broadcast
                ulonglong2 q1 = *(const ulonglong2*)(Pp + b*PROW + 4);  // broadcast
                float p8 = Pp[b*PROW + 8];                              // broadcast
                float2 wv = *(const float2*)(Wcur + b*64 + 2*l);
                const float wf[2] = {wv.x, wv.y};
                #pragma unroll
                for (int i = 0; i < 2; ++i) {
                    ull ww = packf2(wf[i], wf[i]);
                    ffma2(a2p[i][0], ww, q0.x);
                    ffma2(a2p[i][1], ww, q0.y);
                    ffma2(a2p[i][2], ww, q1.x);
                    ffma2(a2p[i][3], ww, q1.y);
                    a2s[i] = fmaf(wf[i], p8, a2s[i]);
                }
            }
        } else if (LO == 1) {
            #pragma unroll 4
            for (int b = 0; b < 64; ++b) {
                ull p01 = *(const ull*)(Pp + b*PROW);
                float p2 = Pp[b*PROW + 2];
                float2 wv = *(const float2*)(Wcur + b*64 + 2*l);
                const float wf[2] = {wv.x, wv.y};
                #pragma unroll
                for (int i = 0; i < 2; ++i) {
                    ull ww = packf2(wf[i], wf[i]);
                    ffma2(a1p[i], ww, p01);
                    a1s[i] = fmaf(wf[i], p2, a1s[i]);
                }
            }
        } else {
            #pragma unroll 4
            for (int b = 0; b < 64; ++b) {
                float p0 = Pp[b*PROW];
                float2 wv = *(const float2*)(Wcur + b*64 + 2*l);
                acc0[0] = fmaf(wv.x, p0, acc0[0]);
                acc0[1] = fmaf(wv.y, p0, acc0[1]);
            }
        }
        __syncthreads();   // P + Wbuf free for next step

        if (++a == 64) { a = 0; ++p; }
    }

    // ---- epilogue: each lane writes its (elem, 2 channels); every slot once ----
    float* o = out + ((size_t)blk*TB + w)*FEAT;
    #pragma unroll
    for (int i = 0; i < 2; ++i) {
        const int c = 2*l + i;
        o[c] = acc0[i];
        float t0, t1;
        unpackf2(a1p[i], t0, t1);
        o[64 + c*3 + 0] = t0; o[64 + c*3 + 1] = t1; o[64 + c*3 + 2] = a1s[i];
        float* o2 = o + 256 + c*9;
        unpackf2(a2p[i][0], t0, t1); o2[0]=t0; o2[1]=t1;
        unpackf2(a2p[i][1], t0, t1); o2[2]=t0; o2[3]=t1;
        unpackf2(a2p[i][2], t0, t1); o2[4]=t0; o2[5]=t1;
        unpackf2(a2p[i][3], t0, t1); o2[6]=t0; o2[7]=t1;
        o2[8] = a2s[i];
    }
}

extern "C" void kernel_launch(void* const* d_in, const int* in_sizes, int n_in,
                              void* d_out, int out_size)
{
    const float* x1  = (const float*)d_in[0];
    const float* x2  = (const float*)d_in[1];
    const float* wgt = (const float*)d_in[2];
    float* out = (float*)d_out;

    const int nbatch = in_sizes[0] / FEAT;     // 4096
    const int grid   = nbatch / TB;            // 512

    tp_transpose<<<NSTEPS, 256>>>(wgt);

    cudaFuncSetAttribute(tp_main, cudaFuncAttributeMaxDynamicSharedMemorySize, SMEM_BYTES);
    tp_main<<<grid, NT, SMEM_BYTES>>>(x1, x2, out);
}

// round 10
// speedup vs baseline: 1.8437x; 1.8437x over previous
#include <cuda_runtime.h>
#include <cuda_bf16.h>
#include <cstdint>
#include <cstddef>

#define FEAT   832
#define NPATH  15
#define WSZ    262144
#define NSTEPS 960
#define TB     16
#define NT     512

// smem byte offsets
#define SM_W   0        // 2 x 16384: W ring (128 rows x 128B: rows 0-63 hi, 64-127 lo), XOR16-swizzled
#define SM_P   32768    // P tile: hi 18432 | lo 18432 (rows = output col, 128B = 64 bf16 over b)
#define SM_IN1 69632    // x1 tile flat [16][832] f32
#define SM_IN2 122880   // x2 tile b-major: Bt0[1024] | Bt1[3072] | Bt2[9216] f32
#define SMEM_BYTES 176128

__constant__ int c_L1[NPATH]={0,0,0,1,1,1,1,1,1,2,2,2,2,2,2};
__constant__ int c_L2[NPATH]={0,1,2,0,1,1,1,2,2,0,1,1,2,2,2};
__constant__ int c_LO[NPATH]={0,1,2,1,2,0,1,1,2,2,1,2,2,0,1};

// Pre-split weights: per step s, 128 rows x 64 bf16 (rows c: hi(W[c][b]), rows c+64: lo), swizzled.
__device__ __nv_bfloat16 g_wa[(size_t)NSTEPS*8192];

__device__ __forceinline__ uint32_t smem_u32(const void* p){
    uint32_t a;
    asm("{ .reg .u64 t; cvta.to.shared.u64 t, %1; cvt.u32.u64 %0, t; }" : "=r"(a) : "l"(p));
    return a;
}
__device__ __forceinline__ void cpasync16(uint32_t dst, const void* src){
    asm volatile("cp.async.cg.shared.global [%0], [%1], 16;" :: "r"(dst), "l"(src));
}
__device__ __forceinline__ void ldsm_x4(uint32_t* r, uint32_t a){
    asm volatile("ldmatrix.sync.aligned.m8n8.x4.shared.b16 {%0,%1,%2,%3}, [%4];"
        : "=r"(r[0]),"=r"(r[1]),"=r"(r[2]),"=r"(r[3]) : "r"(a));
}
__device__ __forceinline__ void ldsm_x2(uint32_t& b0, uint32_t& b1, uint32_t a){
    asm volatile("ldmatrix.sync.aligned.m8n8.x2.shared.b16 {%0,%1}, [%2];"
        : "=r"(b0),"=r"(b1) : "r"(a));
}
__device__ __forceinline__ void mma16816(float* c, const uint32_t* a, uint32_t b0, uint32_t b1){
    asm volatile("mma.sync.aligned.m16n8k16.row.col.f32.bf16.bf16.f32 "
        "{%0,%1,%2,%3}, {%4,%5,%6,%7}, {%8,%9}, {%0,%1,%2,%3};"
        : "+f"(c[0]),"+f"(c[1]),"+f"(c[2]),"+f"(c[3])
        : "r"(a[0]),"r"(a[1]),"r"(a[2]),"r"(a[3]), "r"(b0), "r"(b1));
}

// ---- prep: wgt[p][c][a*64+b] -> per-step [Whi;Wlo] bf16 tiles, XOR16-swizzled ----
__global__ void __launch_bounds__(256)
wprep(const float* __restrict__ wgt)
{
    const int s = blockIdx.x;               // 0..959
    const int p = s>>6, a = s&63;
    const int tid = threadIdx.x;
    const int r = tid>>1, k0 = (tid&1)*32;  // row 0..127, 32 b's
    const float* src = wgt + (size_t)p*WSZ + (size_t)(r&63)*4096 + a*64 + k0;
    __align__(16) __nv_bfloat16 v[32];
    if (r < 64) {
        #pragma unroll
        for (int k=0;k<32;++k) v[k] = __float2bfloat16(src[k]);
    } else {
        #pragma unroll
        for (int k=0;k<32;++k){
            float f = src[k];
            __nv_bfloat16 h = __float2bfloat16(f);
            v[k] = __float2bfloat16(f - __bfloat162float(h));
        }
    }
    char* dst = (char*)(g_wa + (size_t)s*8192);
    const uint32_t xo = (uint32_t)(r&7)<<4;
    #pragma unroll
    for (int ci=0; ci<4; ++ci){
        uint32_t off = (uint32_t)r*128 + ((uint32_t)((k0+ci*8)*2) ^ xo);
        *(uint4*)(dst + off) = *(const uint4*)(v + ci*8);
    }
}

#define BV(x) Bv[(x)*64]

__global__ void __launch_bounds__(NT,1)
tp_mma(const float* __restrict__ x1, const float* __restrict__ x2, float* __restrict__ out)
{
    extern __shared__ char smc[];
    float* As  = (float*)(smc + SM_IN1);
    float* Bst = (float*)(smc + SM_IN2);
    const int tid = threadIdx.x;
    const int l = tid&31, w = tid>>5;
    const int mg = w&1, ng = w>>1;          // warp role: m-group (2 m16-tiles), n-group
    const int blk = blockIdx.x;
    const uint32_t smb = smem_u32(smc);

    // ---- input staging ----
    {
        const float4* g1 = (const float4*)(x1 + (size_t)blk*TB*FEAT);
        float4* s1 = (float4*)As;
        for (int i=tid; i<TB*FEAT/4; i+=NT) s1[i] = g1[i];
    }
    {
        const float* g2 = x2 + (size_t)blk*TB*FEAT;
        for (int i=tid; i<TB*FEAT; i+=NT){
            float v = g2[i];
            int n = i/FEAT, f = i%FEAT, d;
            if (f < 64)       { d = n*64 + f; }
            else if (f < 256) { int g=f-64;  d = 1024 + (n*3 + g%3)*64 + g/3; }
            else              { int g=f-256; d = 4096 + (n*9 + g%9)*64 + g/9; }
            Bst[d] = v;
        }
    }
    {   // W(0) prefetch: 512 thr x 32B = 16KB
        const char* src = (const char*)g_wa + (size_t)tid*32;
        uint32_t dst = smb + SM_W + tid*32;
        cpasync16(dst, src); cpasync16(dst+16, src+16);
        asm volatile("cp.async.commit_group;");
    }
    __syncthreads();

    // ---- persistent accumulators: [slot][m-tile][frag]; slot s -> n-tile ng+8s (s<3), 24+ng (s=3)
    float acc[4][2][4] = {};

    #pragma unroll 1
    for (int s=0; s<NSTEPS; ++s){
        const int p = s>>6, a = s&63;
        const int L1=c_L1[p], L2=c_L2[p], LO=c_LO[p];
        const int mdim = (LO==0)?1:(LO==1)?3:9;
        const int aoff = (L1==0)? a : (L1==1)? 64+a*3 : 256+a*9;

        // ---- pair compute into registers ----
        float Pv[2][9];
        #pragma unroll
        for (int it=0; it<2; ++it){
            const int pr = tid + it*NT;            // 0..1023
            const int n = pr>>6, b = pr&63;
            const float* Aa = As + n*FEAT + aoff;
            const float* Bv = Bst + ((L2==0)? n*64 : (L2==1)? 1024+n*192 : 4096+n*576) + b;
            float* P = Pv[it];
            switch(p){
            case 0:  P[0] = Aa[0]*BV(0); break;
            case 1:  { float v=Aa[0]; P[0]=v*BV(0); P[1]=v*BV(1); P[2]=v*BV(2); } break;
            case 2:  {
                       float v=Aa[0];
                       #pragma unroll
                       for (int j=0;j<9;++j) P[j]=v*BV(j);
                     } break;
            case 3:  { float v=BV(0); P[0]=Aa[0]*v; P[1]=Aa[1]*v; P[2]=Aa[2]*v; } break;
            case 4:  { float u0=Aa[0],u1=Aa[1],u2=Aa[2],v0=BV(0),v1=BV(1),v2=BV(2);
                       P[0]=u0*v0;P[1]=u0*v1;P[2]=u0*v2;
                       P[3]=u1*v0;P[4]=u1*v1;P[5]=u1*v2;
                       P[6]=u2*v0;P[7]=u2*v1;P[8]=u2*v2; } break;
            case 5:  P[0] = Aa[0]*BV(0)+Aa[1]*BV(1)+Aa[2]*BV(2); break;
            case 6:  { float u0=Aa[0],u1=Aa[1],u2=Aa[2],v0=BV(0),v1=BV(1),v2=BV(2);
                       P[0]=u1*v2-u2*v1; P[1]=u2*v0-u0*v2; P[2]=u0*v1-u1*v0; } break;
            case 7:  { float u0=Aa[0],u1=Aa[1],u2=Aa[2];
                       P[0]=u0*BV(0)+u1*BV(1)+u2*BV(2);
                       P[1]=u0*BV(3)+u1*BV(4)+u2*BV(5);
                       P[2]=u0*BV(6)+u1*BV(7)+u2*BV(8); } break;
            case 8:  {
                       float u0=Aa[0],u1=Aa[1],u2=Aa[2];
                       #pragma unroll
                       for (int q=0;q<3;++q){
                           float v0=BV(q*3),v1=BV(q*3+1),v2=BV(q*3+2);
                           P[q*3+0]=u1*v2-u2*v1; P[q*3+1]=u2*v0-u0*v2; P[q*3+2]=u0*v1-u1*v0;
                       }
                     } break;
            case 9:  {
                       float v=BV(0);
                       #pragma unroll
                       for (int j=0;j<9;++j) P[j]=Aa[j]*v;
                     } break;
            case 10: { float v0=BV(0),v1=BV(1),v2=BV(2);
                       P[0]=Aa[0]*v0+Aa[1]*v1+Aa[2]*v2;
                       P[1]=Aa[3]*v0+Aa[4]*v1+Aa[5]*v2;
                       P[2]=Aa[6]*v0+Aa[7]*v1+Aa[8]*v2; } break;
            case 11: {
                       float v0=BV(0),v1=BV(1),v2=BV(2);
                       #pragma unroll
                       for (int d=0;d<3;++d){
                           float u0=Aa[d*3],u1=Aa[d*3+1],u2=Aa[d*3+2];
                           P[d*3+0]=u1*v2-u2*v1; P[d*3+1]=u2*v0-u0*v2; P[d*3+2]=u0*v1-u1*v0;
                       }
                     } break;
            case 12: {
                       #pragma unroll
                       for (int d=0;d<3;++d){
                           float u0=Aa[d*3],u1=Aa[d*3+1],u2=Aa[d*3+2];
                           #pragma unroll
                           for (int f=0;f<3;++f)
                               P[d*3+f]=u0*BV(f*3)+u1*BV(f*3+1)+u2*BV(f*3+2);
                       }
                     } break;
            case 13: {
                       float v=0.f;
                       #pragma unroll
                       for (int j=0;j<9;++j) v += Aa[j]*BV(j);
                       P[0]=v;
                     } break;
            default: {
                       float M01=Aa[0]*BV(3)+Aa[1]*BV(4)+Aa[2]*BV(5);
                       float M02=Aa[0]*BV(6)+Aa[1]*BV(7)+Aa[2]*BV(8);
                       float M10=Aa[3]*BV(0)+Aa[4]*BV(1)+Aa[5]*BV(2);
                       float M12=Aa[3]*BV(6)+Aa[4]*BV(7)+Aa[5]*BV(8);
                       float M20=Aa[6]*BV(0)+Aa[7]*BV(1)+Aa[8]*BV(2);
                       float M21=Aa[6]*BV(3)+Aa[7]*BV(4)+Aa[8]*BV(5);
                       P[0]=M12-M21; P[1]=M20-M02; P[2]=M01-M10; } break;
            }
        }

        __syncthreads();   // all warps done reading P in step s-1 MMA phase

        // ---- store P hi/lo bf16 (rows = output col, swizzled) ----
        {
            const uint32_t pbh = smb + SM_P, pbl = pbh + 18432u;
            #pragma unroll
            for (int it=0; it<2; ++it){
                const int pr = tid + it*NT;
                const int n = pr>>6, b = pr&63;
                #pragma unroll
                for (int m=0;m<9;++m) if (m < mdim){
                    float v = Pv[it][m];
                    __nv_bfloat16 hi = __float2bfloat16(v);
                    __nv_bfloat16 lo = __float2bfloat16(v - __bfloat162float(hi));
                    const int row = n*mdim + m;
                    uint32_t off = (uint32_t)row*128 + (uint32_t)(((((b>>3) ^ (row&7)))<<4) | ((b&7)*2));
                    unsigned short hs = __bfloat16_as_ushort(hi);
                    unsigned short ls = __bfloat16_as_ushort(lo);
                    asm volatile("st.shared.b16 [%0], %1;" :: "r"(pbh+off), "h"(hs));
                    asm volatile("st.shared.b16 [%0], %1;" :: "r"(pbl+off), "h"(ls));
                }
            }
        }

        // ---- prefetch W(s+1) (into buffer freed by MMA(s-1)) ----
        if (s+1 < NSTEPS){
            const char* src = (const char*)g_wa + (size_t)(s+1)*16384 + (size_t)tid*32;
            uint32_t dst = smb + SM_W + (uint32_t)((s+1)&1)*16384u + tid*32;
            cpasync16(dst, src); cpasync16(dst+16, src+16);
        }
        asm volatile("cp.async.commit_group;");
        asm volatile("cp.async.wait_group 1;" ::: "memory");   // W(s) landed
        __syncthreads();                                       // P + W visible to all

        // ---- MMA phase ----
        const bool active = (LO==2) || ((LO==1) ? (ng>=2) : (ng<2));
        if (active){
            const uint32_t wb  = smb + SM_W + (uint32_t)(s&1)*16384u;
            const uint32_t pbh = smb + SM_P, pbl = pbh + 18432u;
            const int grp = l>>3, lr = l&7;
            #pragma unroll
            for (int k=0;k<4;++k){
                uint32_t ah[2][4], al[2][4];
                #pragma unroll
                for (int mt=0; mt<2; ++mt){
                    const int rb = mg*32 + mt*16;
                    {   // hi rows
                        int row = rb + (grp&1)*8 + lr;
                        int ch  = 2*k + (grp>>1);
                        ldsm_x4(ah[mt], wb + (uint32_t)(row*128 + ((ch ^ (row&7))<<4)));
                    }
                    {   // lo rows (+64)
                        int row = 64 + rb + (grp&1)*8 + lr;
                        int ch  = 2*k + (grp>>1);
                        ldsm_x4(al[mt], wb + (uint32_t)(row*128 + ((ch ^ (row&7))<<4)));
                    }
                }
                auto doslot = [&](float (*am)[4], int lt){
                    const int brow = lt*8 + lr;
                    const int bch  = 2*k + (grp&1);
                    const uint32_t ba = (uint32_t)(brow*128 + ((bch ^ (brow&7))<<4));
                    uint32_t bh0,bh1,bl0,bl1;
                    ldsm_x2(bh0,bh1, pbh+ba);
                    ldsm_x2(bl0,bl1, pbl+ba);
                    #pragma unroll
                    for (int mt=0; mt<2; ++mt){
                        mma16816(am[mt], ah[mt], bh0, bh1);
                        mma16816(am[mt], ah[mt], bl0, bl1);
                        mma16816(am[mt], al[mt], bh0, bh1);
                    }
                };
                if (LO==2){
                    doslot(acc[0], ng);
                    doslot(acc[1], ng+8);
                    if (ng<2) doslot(acc[2], ng+16);
                } else if (LO==1){
                    doslot(acc[2], ng-2);
                } else {
                    doslot(acc[3], ng);
                }
            }
        }
    }

    // ---- epilogue: each warp writes its tiles; every output slot exactly once ----
    const int g = l>>2, tig = l&3;
    float* ob = out + (size_t)blk*TB*FEAT;
    #pragma unroll
    for (int sl=0; sl<4; ++sl){
        if (sl==3 && ng>=2) continue;
        const int t = (sl<3)? (ng + 8*sl) : (24 + ng);
        #pragma unroll
        for (int mt=0; mt<2; ++mt){
            const int c0 = mg*32 + mt*16 + g;
            #pragma unroll
            for (int fr=0; fr<4; ++fr){
                const int c  = c0 + ((fr>=2)?8:0);
                const int gc = t*8 + 2*tig + (fr&1);
                int n, f;
                if (gc < 144)      { n = gc/9;            f = 256 + c*9 + gc%9; }
                else if (gc < 192) { int lc=gc-144; n=lc/3; f = 64 + c*3 + lc%3; }
                else               { n = gc-192;          f = c; }
                ob[(size_t)n*FEAT + f] = acc[sl][mt][fr];
            }
        }
    }
}

extern "C" void kernel_launch(void* const* d_in, const int* in_sizes, int n_in,
                              void* d_out, int out_size)
{
    const float* x1  = (const float*)d_in[0];
    const float* x2  = (const float*)d_in[1];
    const float* wgt = (const float*)d_in[2];
    float* out = (float*)d_out;

    const int nbatch = in_sizes[0] / FEAT;     // 4096
    const int grid   = nbatch / TB;            // 256

    wprep<<<NSTEPS, 256>>>(wgt);

    cudaFuncSetAttribute(tp_mma, cudaFuncAttributeMaxDynamicSharedMemorySize, SMEM_BYTES);
    tp_mma<<<grid, NT, SMEM_BYTES>>>(x1, x2, out);
}

// round 15
// speedup vs baseline: 1.9544x; 1.0600x over previous
#include <cuda_runtime.h>
#include <cuda_bf16.h>
#include <cstdint>
#include <cstddef>

#define FEAT   832
#define NPATH  15
#define WSZ    262144
#define NSTEPS 960
#define TB     16
#define NT     512

// smem byte offsets
#define SM_W   0        // 3 x 16384: W ring (128 rows x 128B: rows 0-63 hi, 64-127 lo), XOR16-swizzled
#define SM_P   49152    // 2 x (hi 18432 | lo 18432) P ring (rows = output col)
#define SM_IN2 122880   // x2 tile b-major: Bt0[1024] | Bt1[3072] | Bt2[9216] f32
#define SMEM_BYTES 176128

__constant__ int c_L1[NPATH]={0,0,0,1,1,1,1,1,1,2,2,2,2,2,2};
__constant__ int c_L2[NPATH]={0,1,2,0,1,1,1,2,2,0,1,1,2,2,2};
__constant__ int c_LO[NPATH]={0,1,2,1,2,0,1,1,2,2,1,2,2,0,1};

// Pre-split weights: per step s, 128 rows x 64 bf16 (rows c: hi(W[c][b]), rows c+64: lo), swizzled.
__device__ __nv_bfloat16 g_wa[(size_t)NSTEPS*8192];

__device__ __forceinline__ uint32_t smem_u32(const void* p){
    uint32_t a;
    asm("{ .reg .u64 t; cvta.to.shared.u64 t, %1; cvt.u32.u64 %0, t; }" : "=r"(a) : "l"(p));
    return a;
}
__device__ __forceinline__ void cpasync16(uint32_t dst, const void* src){
    asm volatile("cp.async.cg.shared.global [%0], [%1], 16;" :: "r"(dst), "l"(src));
}
__device__ __forceinline__ void ldsm_x4(uint32_t* r, uint32_t a){
    asm volatile("ldmatrix.sync.aligned.m8n8.x4.shared.b16 {%0,%1,%2,%3}, [%4];"
        : "=r"(r[0]),"=r"(r[1]),"=r"(r[2]),"=r"(r[3]) : "r"(a));
}
__device__ __forceinline__ void ldsm_x2(uint32_t& b0, uint32_t& b1, uint32_t a){
    asm volatile("ldmatrix.sync.aligned.m8n8.x2.shared.b16 {%0,%1}, [%2];"
        : "=r"(b0),"=r"(b1) : "r"(a));
}
__device__ __forceinline__ void mma16816(float* c, const uint32_t* a, uint32_t b0, uint32_t b1){
    asm volatile("mma.sync.aligned.m16n8k16.row.col.f32.bf16.bf16.f32 "
        "{%0,%1,%2,%3}, {%4,%5,%6,%7}, {%8,%9}, {%0,%1,%2,%3};"
        : "+f"(c[0]),"+f"(c[1]),"+f"(c[2]),"+f"(c[3])
        : "r"(a[0]),"r"(a[1]),"r"(a[2]),"r"(a[3]), "r"(b0), "r"(b1));
}

// ---- prep: wgt[p][c][a*64+b] -> per-step [Whi;Wlo] bf16 tiles, XOR16-swizzled ----
__global__ void __launch_bounds__(256)
wprep(const float* __restrict__ wgt)
{
    const int s = blockIdx.x;               // 0..959
    const int p = s>>6, a = s&63;
    const int tid = threadIdx.x;
    const int r = tid>>1, k0 = (tid&1)*32;
    const float* src = wgt + (size_t)p*WSZ + (size_t)(r&63)*4096 + a*64 + k0;
    __align__(16) __nv_bfloat16 v[32];
    if (r < 64) {
        #pragma unroll
        for (int k=0;k<32;++k) v[k] = __float2bfloat16(src[k]);
    } else {
        #pragma unroll
        for (int k=0;k<32;++k){
            float f = src[k];
            __nv_bfloat16 h = __float2bfloat16(f);
            v[k] = __float2bfloat16(f - __bfloat162float(h));
        }
    }
    char* dst = (char*)(g_wa + (size_t)s*8192);
    const uint32_t xo = (uint32_t)(r&7)<<4;
    #pragma unroll
    for (int ci=0; ci<4; ++ci){
        uint32_t off = (uint32_t)r*128 + ((uint32_t)((k0+ci*8)*2) ^ xo);
        *(uint4*)(dst + off) = *(const uint4*)(v + ci*8);
    }
}

#define BV(x) Bb[x]

__global__ void __launch_bounds__(NT,1)
tp_mma(const float* __restrict__ x1, const float* __restrict__ x2, float* __restrict__ out)
{
    extern __shared__ char smc[];
    float* Bst = (float*)(smc + SM_IN2);
    const int tid = threadIdx.x;
    const int l = tid&31, w = tid>>5;
    const int mg = w&1, ng = w>>1;          // MMA role: m-group, n-group
    const int blk = blockIdx.x;
    const uint32_t smb = smem_u32(smc);

    // ---- x2 -> b-major staging ----
    {
        const float* g2 = x2 + (size_t)blk*TB*FEAT;
        for (int i=tid; i<TB*FEAT; i+=NT){
            float v = g2[i];
            int n = i/FEAT, f = i%FEAT, d;
            if (f < 64)       { d = n*64 + f; }
            else if (f < 256) { int g=f-64;  d = 1024 + (n*3 + g%3)*64 + g/3; }
            else              { int g=f-256; d = 4096 + (n*9 + g%9)*64 + g/9; }
            Bst[d] = v;
        }
    }
    {   // W(0) prefetch into ring slot 0
        const char* src = (const char*)g_wa + (size_t)tid*32;
        uint32_t dst = smb + SM_W + tid*32;
        cpasync16(dst, src); cpasync16(dst+16, src+16);
        asm volatile("cp.async.commit_group;");
    }
    __syncthreads();

    // persistent accumulators: [slot][m-tile][frag]
    // slot0 -> tile 2ng, slot1 -> 2ng+1, slot2 -> (ng<2)?16+ng:18+(ng-2), slot3 -> 24+ng (ng<2)
    float acc[4][2][4] = {};

    const float* x1row = x1 + ((size_t)blk*TB + w)*FEAT;   // pair phase: warp w = elem w

    #pragma unroll 1
    for (int s=0; s<NSTEPS; ++s){
        const int p = s>>6;
        const int a = s&63;
        const int L1=c_L1[p], L2=c_L2[p], LO=c_LO[p];
        const int mdim = (LO==0)?1:(LO==1)?3:9;
        const int L2d  = (L2==0)?1:(L2==1)?3:9;
        const int aoff = (L1==0)? a : (L1==1)? 64+a*3 : 256+a*9;

        // ---- pair compute: lane handles b = 2l, 2l+1 of elem w ----
        float Pv[2][9];
        {
            const float* Bb2 = Bst + ((L2==0)? w*64 : (L2==1)? 1024+w*192 : 4096+w*576) + 2*l;
            float2 Bf[9];
            #pragma unroll
            for (int j=0;j<9;++j) if (j<L2d) Bf[j] = *(const float2*)(Bb2 + j*64);
            const float* Aa = x1row + aoff;
            #pragma unroll
            for (int bb=0; bb<2; ++bb){
                float Bb[9];
                #pragma unroll
                for (int j=0;j<9;++j) if (j<L2d) Bb[j] = bb ? Bf[j].y : Bf[j].x;
                float* P = Pv[bb];
                switch(p){
                case 0:  P[0] = Aa[0]*BV(0); break;
                case 1:  { float v=Aa[0]; P[0]=v*BV(0); P[1]=v*BV(1); P[2]=v*BV(2); } break;
                case 2:  {
                           float v=Aa[0];
                           #pragma unroll
                           for (int j=0;j<9;++j) P[j]=v*BV(j);
                         } break;
                case 3:  { float v=BV(0); P[0]=Aa[0]*v; P[1]=Aa[1]*v; P[2]=Aa[2]*v; } break;
                case 4:  { float u0=Aa[0],u1=Aa[1],u2=Aa[2],v0=BV(0),v1=BV(1),v2=BV(2);
                           P[0]=u0*v0;P[1]=u0*v1;P[2]=u0*v2;
                           P[3]=u1*v0;P[4]=u1*v1;P[5]=u1*v2;
                           P[6]=u2*v0;P[7]=u2*v1;P[8]=u2*v2; } break;
                case 5:  P[0] = Aa[0]*BV(0)+Aa[1]*BV(1)+Aa[2]*BV(2); break;
                case 6:  { float u0=Aa[0],u1=Aa[1],u2=Aa[2],v0=BV(0),v1=BV(1),v2=BV(2);
                           P[0]=u1*v2-u2*v1; P[1]=u2*v0-u0*v2; P[2]=u0*v1-u1*v0; } break;
                case 7:  { float u0=Aa[0],u1=Aa[1],u2=Aa[2];
                           P[0]=u0*BV(0)+u1*BV(1)+u2*BV(2);
                           P[1]=u0*BV(3)+u1*BV(4)+u2*BV(5);
                           P[2]=u0*BV(6)+u1*BV(7)+u2*BV(8); } break;
                case 8:  {
                           float u0=Aa[0],u1=Aa[1],u2=Aa[2];
                           #pragma unroll
                           for (int q=0;q<3;++q){
                               float v0=BV(q*3),v1=BV(q*3+1),v2=BV(q*3+2);
                               P[q*3+0]=u1*v2-u2*v1; P[q*3+1]=u2*v0-u0*v2; P[q*3+2]=u0*v1-u1*v0;
                           }
                         } break;
                case 9:  {
                           float v=BV(0);
                           #pragma unroll
                           for (int j=0;j<9;++j) P[j]=Aa[j]*v;
                         } break;
                case 10: { float v0=BV(0),v1=BV(1),v2=BV(2);
                           P[0]=Aa[0]*v0+Aa[1]*v1+Aa[2]*v2;
                           P[1]=Aa[3]*v0+Aa[4]*v1+Aa[5]*v2;
                           P[2]=Aa[6]*v0+Aa[7]*v1+Aa[8]*v2; } break;
                case 11: {
                           float v0=BV(0),v1=BV(1),v2=BV(2);
                           #pragma unroll
                           for (int d=0;d<3;++d){
                               float u0=Aa[d*3],u1=Aa[d*3+1],u2=Aa[d*3+2];
                               P[d*3+0]=u1*v2-u2*v1; P[d*3+1]=u2*v0-u0*v2; P[d*3+2]=u0*v1-u1*v0;
                           }
                         } break;
                case 12: {
                           #pragma unroll
                           for (int d=0;d<3;++d){
                               float u0=Aa[d*3],u1=Aa[d*3+1],u2=Aa[d*3+2];
                               #pragma unroll
                               for (int f=0;f<3;++f)
                                   P[d*3+f]=u0*BV(f*3)+u1*BV(f*3+1)+u2*BV(f*3+2);
                           }
                         } break;
                case 13: {
                           float v=0.f;
                           #pragma unroll
                           for (int j=0;j<9;++j) v += Aa[j]*BV(j);
                           P[0]=v;
                         } break;
                default: {
                           float M01=Aa[0]*BV(3)+Aa[1]*BV(4)+Aa[2]*BV(5);
                           float M02=Aa[0]*BV(6)+Aa[1]*BV(7)+Aa[2]*BV(8);
                           float M10=Aa[3]*BV(0)+Aa[4]*BV(1)+Aa[5]*BV(2);
                           float M12=Aa[3]*BV(6)+Aa[4]*BV(7)+Aa[5]*BV(8);
                           float M20=Aa[6]*BV(0)+Aa[7]*BV(1)+Aa[8]*BV(2);
                           float M21=Aa[6]*BV(3)+Aa[7]*BV(4)+Aa[8]*BV(5);
                           P[0]=M12-M21; P[1]=M20-M02; P[2]=M01-M10; } break;
                }
            }
        }

        // ---- store P(s): packed bf16x2 (b=2l,2l+1), hi + lo tiles ----
        {
            const uint32_t pbh = smb + SM_P + (uint32_t)(s&1)*36864u;
            const uint32_t pbl = pbh + 18432u;
            #pragma unroll
            for (int m=0;m<9;++m) if (m<mdim){
                float p0 = Pv[0][m], p1 = Pv[1][m];
                __nv_bfloat162 h2 = __float22bfloat162_rn(make_float2(p0,p1));
                float r0 = p0 - __bfloat162float(h2.x);
                float r1 = p1 - __bfloat162float(h2.y);
                __nv_bfloat162 l2v = __float22bfloat162_rn(make_float2(r0,r1));
                const int row = w*mdim + m;
                uint32_t off = (uint32_t)row*128 + (uint32_t)(((((l>>2) ^ (row&7)))<<4) + (l&3)*4);
                uint32_t hu = *reinterpret_cast<uint32_t*>(&h2);
                uint32_t lu = *reinterpret_cast<uint32_t*>(&l2v);
                asm volatile("st.shared.b32 [%0], %1;" :: "r"(pbh+off), "r"(hu));
                asm volatile("st.shared.b32 [%0], %1;" :: "r"(pbl+off), "r"(lu));
            }
        }

        // ---- prefetch W(s+1) into ring slot (s+1)%3 ----
        if (s+1 < NSTEPS){
            const char* src = (const char*)g_wa + (size_t)(s+1)*16384 + (size_t)tid*32;
            uint32_t dst = smb + SM_W + (uint32_t)((s+1)%3)*16384u + tid*32;
            cpasync16(dst, src); cpasync16(dst+16, src+16);
        }
        asm volatile("cp.async.commit_group;");
        asm volatile("cp.async.wait_group 1;" ::: "memory");   // W(s) landed
        __syncthreads();                                       // single barrier per step

        // ---- MMA phase ----
        const bool active = (LO==2) || ((LO==1) ? (ng>=2) : (ng<2));
        if (active){
            const uint32_t wb  = smb + SM_W + (uint32_t)(s%3)*16384u;
            const uint32_t pbh = smb + SM_P + (uint32_t)(s&1)*36864u;
            const uint32_t pbl = pbh + 18432u;
            const int lr = l&7, g8 = (l>>3)&1, g16 = (l>>4)&1;
            #pragma unroll
            for (int k=0;k<4;++k){
                uint32_t ah[2][4], al[2][4];
                #pragma unroll
                for (int mt=0; mt<2; ++mt){
                    const int rb = mg*32 + mt*16;
                    int row = rb + g8*8 + lr;
                    int ch  = 2*k + (l>>4);
                    ldsm_x4(ah[mt], wb + (uint32_t)(row*128 + ((ch ^ (row&7))<<4)));
                    row += 64;
                    ldsm_x4(al[mt], wb + (uint32_t)(row*128 + ((ch ^ (row&7))<<4)));
                }
                auto one = [&](float (*am)[4], int lt){
                    const int brow = lt*8 + lr;
                    const int bch  = 2*k + g8;
                    const uint32_t ba = (uint32_t)(brow*128 + ((bch ^ (brow&7))<<4));
                    uint32_t bh0,bh1,bl0,bl1;
                    ldsm_x2(bh0,bh1, pbh+ba);
                    ldsm_x2(bl0,bl1, pbl+ba);
                    #pragma unroll
                    for (int mt=0; mt<2; ++mt){
                        mma16816(am[mt], ah[mt], bh0, bh1);
                        mma16816(am[mt], ah[mt], bl0, bl1);
                        mma16816(am[mt], al[mt], bh0, bh1);
                    }
                };
                auto pairt = [&](float (*am0)[4], float (*am1)[4], int t0){
                    const int brow = (t0 + g16)*8 + lr;
                    const int bch  = 2*k + g8;
                    const uint32_t ba = (uint32_t)(brow*128 + ((bch ^ (brow&7))<<4));
                    uint32_t bh[4], bl[4];
                    ldsm_x4(bh, pbh+ba);
                    ldsm_x4(bl, pbl+ba);
                    #pragma unroll
                    for (int mt=0; mt<2; ++mt){
                        mma16816(am0[mt], ah[mt], bh[0], bh[1]);
                        mma16816(am0[mt], ah[mt], bl[0], bl[1]);
                        mma16816(am0[mt], al[mt], bh[0], bh[1]);
                        mma16816(am1[mt], ah[mt], bh[2], bh[3]);
                        mma16816(am1[mt], ah[mt], bl[2], bl[3]);
                        mma16816(am1[mt], al[mt], bh[2], bh[3]);
                    }
                };
                if (LO==2){
                    pairt(acc[0], acc[1], 2*ng);
                    if (ng<2) one(acc[2], 16+ng);
                } else if (LO==1){
                    one(acc[2], ng-2);
                } else {
                    one(acc[3], ng);
                }
            }
        }
    }

    // ---- epilogue: every output slot exactly once ----
    const int g = l>>2, tig = l&3;
    float* ob = out + (size_t)blk*TB*FEAT;
    #pragma unroll
    for (int sl=0; sl<4; ++sl){
        if (sl==3 && ng>=2) continue;
        int t;
        if (sl==0)      t = 2*ng;
        else if (sl==1) t = 2*ng+1;
        else if (sl==2) t = (ng<2) ? (16+ng) : (18 + (ng-2));
        else            t = 24+ng;
        #pragma unroll
        for (int mt=0; mt<2; ++mt){
            const int c0 = mg*32 + mt*16 + g;
            #pragma unroll
            for (int fr=0; fr<4; ++fr){
                const int c  = c0 + ((fr>=2)?8:0);
                const int gc = t*8 + 2*tig + (fr&1);
                int n, f;
                if (gc < 144)      { n = gc/9;            f = 256 + c*9 + gc%9; }
                else if (gc < 192) { int lc=gc-144; n=lc/3; f = 64 + c*3 + lc%3; }
                else               { n = gc-192;          f = c; }
                ob[(size_t)n*FEAT + f] = acc[sl][mt][fr];
            }
        }
    }
}

extern "C" void kernel_launch(void* const* d_in, const int* in_sizes, int n_in,
                              void* d_out, int out_size)
{
    const float* x1  = (const float*)d_in[0];
    const float* x2  = (const float*)d_in[1];
    const float* wgt = (const float*)d_in[2];
    float* out = (float*)d_out;

    const int nbatch = in_sizes[0] / FEAT;     // 4096
    const int grid   = nbatch / TB;            // 256

    wprep<<<NSTEPS, 256>>>(wgt);

    cudaFuncSetAttribute(tp_mma, cudaFuncAttributeMaxDynamicSharedMemorySize, SMEM_BYTES);
    tp_mma<<<grid, NT, SMEM_BYTES>>>(x1, x2, out);
}